// round 1
// baseline (speedup 1.0000x reference)
#include <cuda_runtime.h>

#define NN   100000
#define DD   128
#define PP   64
#define EE   3200000
#define EPTN 5000000
#define EPSI 0.1f
#define INVN (1.0f/100000.0f)
#define BV   (1.0f/64.0f)

// -------- scratch (device globals; no dynamic allocation allowed) ----------
__device__ float g_deg[NN];
__device__ float g_dis[NN];
__device__ float g_xaggr[NN*DD];
__device__ float g_xs[NN*DD];
__device__ float g_pn[PP*DD];
__device__ float g_K[(size_t)NN*PP];
__device__ float g_t[21*PP];
__device__ float g_xf[NN*DD];
__device__ unsigned int g_wmax;

__device__ __forceinline__ float warp_sum(float v) {
    v += __shfl_xor_sync(0xffffffffu, v, 16);
    v += __shfl_xor_sync(0xffffffffu, v, 8);
    v += __shfl_xor_sync(0xffffffffu, v, 4);
    v += __shfl_xor_sync(0xffffffffu, v, 2);
    v += __shfl_xor_sync(0xffffffffu, v, 1);
    return v;
}

// ---------------------------------------------------------------------------
__global__ void k_init(float* loss_slot) {
    int idx = blockIdx.x * blockDim.x + threadIdx.x;
    if (idx < NN*DD) g_xaggr[idx] = 0.f;
    if (idx < NN)    g_deg[idx]   = 0.f;
    if (idx < 21*PP) g_t[idx]     = 0.f;
    if (idx == 0) { g_wmax = 0u; *loss_slot = 0.f; }
}

__global__ void k_deg(const int* __restrict__ ei) {
    int e = blockIdx.x * blockDim.x + threadIdx.x;
    if (e < EE) atomicAdd(&g_deg[ei[EE + e]], 1.0f);
}

__global__ void k_dis() {
    int i = blockIdx.x * blockDim.x + threadIdx.x;
    if (i < NN) {
        float d = g_deg[i];
        g_dis[i] = (d > 0.f) ? rsqrtf(d) : 0.f;
    }
}

// warp per edge: x_aggr[row] += x[col] * norm_weight
__global__ void k_agg(const int* __restrict__ ei, const float* __restrict__ ew,
                      const float* __restrict__ x) {
    int t = blockIdx.x * blockDim.x + threadIdx.x;
    int e = t >> 5, lane = t & 31;
    if (e >= EE) return;
    int r = ei[e];
    int c = ei[EE + e];
    float nw = g_dis[r] * ew[e] * g_dis[c];
    float4 v = *(const float4*)(x + (size_t)c * DD + lane * 4);
    float* dst = g_xaggr + (size_t)r * DD + lane * 4;
    atomicAdd(dst + 0, v.x * nw);
    atomicAdd(dst + 1, v.y * nw);
    atomicAdd(dst + 2, v.z * nw);
    atomicAdd(dst + 3, v.w * nw);
}

// normalize prompt tokens (warp per prompt)
__global__ void k_pnorm(const float* __restrict__ pt) {
    int t = blockIdx.x * blockDim.x + threadIdx.x;
    int p = t >> 5, lane = t & 31;
    if (p >= PP) return;
    float4 v = *(const float4*)(pt + (size_t)p * DD + lane * 4);
    float ss = warp_sum(v.x*v.x + v.y*v.y + v.z*v.z + v.w*v.w);
    float inv = 1.f / fmaxf(sqrtf(ss), 1e-12f);
    float4 o = make_float4(v.x*inv, v.y*inv, v.z*inv, v.w*inv);
    *(float4*)(g_pn + (size_t)p * DD + lane * 4) = o;
}

// x_struct = (1-g)x + g*x_aggr, l2-normalized -> g_xs  (warp per row)
__global__ void k_xstruct(const float* __restrict__ x, const float* __restrict__ gamma_p) {
    int t = blockIdx.x * blockDim.x + threadIdx.x;
    int r = t >> 5, lane = t & 31;
    if (r >= NN) return;
    float g = *gamma_p;
    float4 xv = *(const float4*)(x       + (size_t)r * DD + lane * 4);
    float4 av = *(const float4*)(g_xaggr + (size_t)r * DD + lane * 4);
    float4 s;
    s.x = (1.f - g) * xv.x + g * av.x;
    s.y = (1.f - g) * xv.y + g * av.y;
    s.z = (1.f - g) * xv.z + g * av.z;
    s.w = (1.f - g) * xv.w + g * av.w;
    float ss = warp_sum(s.x*s.x + s.y*s.y + s.z*s.z + s.w*s.w);
    float inv = 1.f / fmaxf(sqrtf(ss), 1e-12f);
    float4 o = make_float4(s.x*inv, s.y*inv, s.z*inv, s.w*inv);
    *(float4*)(g_xs + (size_t)r * DD + lane * 4) = o;
}

// K[i][p] = exp(10*(cos-1)); also t0[p] = (1/N) * sum_i K[i][p]
// block = 256 threads, tile = 64 rows x 64 prompts, 4x4 per thread
__global__ void k_kbuild() {
    __shared__ float xs_sh[64][68];
    __shared__ float pn_sh[64][68];
    __shared__ float t_sh[PP];
    int tid = threadIdx.x;
    int tx = tid & 15;    // prompt tile
    int ty = tid >> 4;    // row tile
    int rowBase = blockIdx.x * 64;

    float acc[4][4];
#pragma unroll
    for (int i = 0; i < 4; i++)
#pragma unroll
        for (int j = 0; j < 4; j++) acc[i][j] = 0.f;

    for (int ch = 0; ch < 2; ch++) {
#pragma unroll
        for (int i = 0; i < 4; i++) {
            int rr = ty + i * 16;       // 0..63
            int c4 = tx * 4;            // 0..60
            int gr = rowBase + rr;
            float4 v = (gr < NN) ? *(const float4*)(g_xs + (size_t)gr * DD + ch * 64 + c4)
                                 : make_float4(0.f, 0.f, 0.f, 0.f);
            *(float4*)&xs_sh[rr][c4] = v;
            *(float4*)&pn_sh[rr][c4] = *(const float4*)(g_pn + (size_t)rr * DD + ch * 64 + c4);
        }
        __syncthreads();
#pragma unroll 8
        for (int d = 0; d < 64; d += 4) {
            float4 a[4], b[4];
#pragma unroll
            for (int i = 0; i < 4; i++) a[i] = *(float4*)&xs_sh[ty * 4 + i][d];
#pragma unroll
            for (int j = 0; j < 4; j++) b[j] = *(float4*)&pn_sh[tx * 4 + j][d];
#pragma unroll
            for (int i = 0; i < 4; i++)
#pragma unroll
                for (int j = 0; j < 4; j++) {
                    acc[i][j] += a[i].x * b[j].x;
                    acc[i][j] += a[i].y * b[j].y;
                    acc[i][j] += a[i].z * b[j].z;
                    acc[i][j] += a[i].w * b[j].w;
                }
        }
        __syncthreads();
    }

    if (tid < PP) t_sh[tid] = 0.f;
    __syncthreads();

    float colsum[4] = {0.f, 0.f, 0.f, 0.f};
#pragma unroll
    for (int i = 0; i < 4; i++) {
        int gr = rowBase + ty * 4 + i;
        if (gr < NN) {
            float4 kv;
            kv.x = __expf(10.f * (acc[i][0] - 1.f));
            kv.y = __expf(10.f * (acc[i][1] - 1.f));
            kv.z = __expf(10.f * (acc[i][2] - 1.f));
            kv.w = __expf(10.f * (acc[i][3] - 1.f));
            *(float4*)(g_K + (size_t)gr * PP + tx * 4) = kv;
            colsum[0] += kv.x; colsum[1] += kv.y; colsum[2] += kv.z; colsum[3] += kv.w;
        }
    }
#pragma unroll
    for (int j = 0; j < 4; j++) atomicAdd(&t_sh[tx * 4 + j], colsum[j]);
    __syncthreads();
    if (tid < PP) atomicAdd(&g_t[tid], t_sh[tid] * INVN);
}

// one Sinkhorn iteration: v = b/(t_prev+eps); u_i = a/(K_i.v+eps); t_new += K^T u
__global__ void k_sink(int iter) {
    __shared__ float v_sh[PP];
    int tid = threadIdx.x;
    if (tid < PP) v_sh[tid] = BV / (g_t[(iter - 1) * PP + tid] + 1e-30f);
    __syncthreads();
    int lane = tid & 31;
    int warpId = (blockIdx.x * blockDim.x + tid) >> 5;
    int nW = (gridDim.x * blockDim.x) >> 5;
    float v0 = v_sh[2 * lane], v1 = v_sh[2 * lane + 1];
    float a0 = 0.f, a1 = 0.f;
    for (int r = warpId; r < NN; r += nW) {
        float2 k2 = *(const float2*)(g_K + (size_t)r * PP + 2 * lane);
        float s = warp_sum(k2.x * v0 + k2.y * v1);
        float u = INVN / (s + 1e-30f);
        a0 += k2.x * u;
        a1 += k2.y * u;
    }
    atomicAdd(&g_t[iter * PP + 2 * lane],     a0);
    atomicAdd(&g_t[iter * PP + 2 * lane + 1], a1);
}

// epilogue: v20, u20, T*, ot_loss, prompt_message, x_adapted, xf
// block = 128 threads (4 warps), warp handles groups of 8 rows
__global__ void k_epi(const float* __restrict__ x, const float* __restrict__ pt,
                      const float* __restrict__ alpha_p,
                      float* __restrict__ out_x, float* __restrict__ loss_out) {
    __shared__ float pt_sh[PP][DD];    // raw prompt tokens, 32 KB
    __shared__ float T_sh[4][8][PP];   // 8 KB
    __shared__ float v_sh[PP];
    int tid = threadIdx.x;
    for (int i = tid; i < PP * DD / 4; i += blockDim.x)
        ((float4*)&pt_sh[0][0])[i] = ((const float4*)pt)[i];
    if (tid < PP) v_sh[tid] = BV / (g_t[19 * PP + tid] + 1e-30f);
    __syncthreads();

    int lane = tid & 31, w = tid >> 5;
    int warpId = (blockIdx.x * blockDim.x + tid) >> 5;
    int nW = (gridDim.x * blockDim.x) >> 5;
    float v0 = v_sh[2 * lane], v1 = v_sh[2 * lane + 1];
    float scaleA = (*alpha_p) * (float)NN;
    float lossAcc = 0.f;

    for (int base = warpId * 8; base < NN; base += nW * 8) {
#pragma unroll
        for (int rr = 0; rr < 8; rr++) {
            int r = base + rr;
            float2 k2 = *(const float2*)(g_K + (size_t)r * PP + 2 * lane);
            float s = warp_sum(k2.x * v0 + k2.y * v1);
            float u = INVN / (s + 1e-30f);
            float T0 = u * k2.x * v0;
            float T1 = u * k2.y * v1;
            lossAcc += T0 * (-EPSI * __logf(k2.x)) + T1 * (-EPSI * __logf(k2.y));
            T_sh[w][rr][2 * lane]     = T0;
            T_sh[w][rr][2 * lane + 1] = T1;
        }
        __syncwarp();
        float4 pm[8];
#pragma unroll
        for (int rr = 0; rr < 8; rr++) pm[rr] = make_float4(0.f, 0.f, 0.f, 0.f);
#pragma unroll 4
        for (int p = 0; p < PP; p++) {
            float4 pv = *(const float4*)&pt_sh[p][lane * 4];
#pragma unroll
            for (int rr = 0; rr < 8; rr++) {
                float tp = T_sh[w][rr][p];
                pm[rr].x += tp * pv.x;
                pm[rr].y += tp * pv.y;
                pm[rr].z += tp * pv.z;
                pm[rr].w += tp * pv.w;
            }
        }
#pragma unroll
        for (int rr = 0; rr < 8; rr++) {
            int r = base + rr;
            float4 xv = *(const float4*)(x + (size_t)r * DD + lane * 4);
            float4 o;
            o.x = xv.x + scaleA * pm[rr].x;
            o.y = xv.y + scaleA * pm[rr].y;
            o.z = xv.z + scaleA * pm[rr].z;
            o.w = xv.w + scaleA * pm[rr].w;
            *(float4*)(out_x + (size_t)r * DD + lane * 4) = o;
            float ss = warp_sum(o.x*o.x + o.y*o.y + o.z*o.z + o.w*o.w);
            float inv = 1.f / fmaxf(sqrtf(ss), 1e-12f);
            float4 f = make_float4(o.x*inv, o.y*inv, o.z*inv, o.w*inv);
            *(float4*)(g_xf + (size_t)r * DD + lane * 4) = f;
        }
        __syncwarp();
    }
    lossAcc = warp_sum(lossAcc);
    if (lane == 0) atomicAdd(loss_out, lossAcc);
}

// w_e = relu(dot(xf[r], xf[c])); track global max. Warp processes 32-edge batches.
__global__ void k_w(const int* __restrict__ ptei, float* __restrict__ w_out) {
    int tid = threadIdx.x;
    int lane = tid & 31;
    int warpId = (blockIdx.x * blockDim.x + tid) >> 5;
    int nW = (gridDim.x * blockDim.x) >> 5;
    float wmax = 0.f;
    for (int base = warpId * 32; base < EPTN; base += nW * 32) {
        int e = base + lane;
        int r = ptei[e];
        int c = ptei[EPTN + e];
        float myW = 0.f;
        for (int k = 0; k < 32; k++) {
            int rk = __shfl_sync(0xffffffffu, r, k);
            int ck = __shfl_sync(0xffffffffu, c, k);
            float4 a = *(const float4*)(g_xf + (size_t)rk * DD + lane * 4);
            float4 b = *(const float4*)(g_xf + (size_t)ck * DD + lane * 4);
            float s = warp_sum(a.x*b.x + a.y*b.y + a.z*b.z + a.w*b.w);
            if (lane == k) myW = s;
        }
        myW = fmaxf(myW, 0.f);
        w_out[e] = myW;
        wmax = fmaxf(wmax, myW);
    }
    wmax = fmaxf(wmax, __shfl_xor_sync(0xffffffffu, wmax, 16));
    wmax = fmaxf(wmax, __shfl_xor_sync(0xffffffffu, wmax, 8));
    wmax = fmaxf(wmax, __shfl_xor_sync(0xffffffffu, wmax, 4));
    wmax = fmaxf(wmax, __shfl_xor_sync(0xffffffffu, wmax, 2));
    wmax = fmaxf(wmax, __shfl_xor_sync(0xffffffffu, wmax, 1));
    if (lane == 0) atomicMax(&g_wmax, __float_as_uint(wmax));
}

__global__ void k_wnorm(float* __restrict__ w_out) {
    int i = blockIdx.x * blockDim.x + threadIdx.x;
    if (i < EPTN) {
        float sc = 1.f / (__uint_as_float(g_wmax) + 1e-8f);
        w_out[i] *= sc;
    }
}

// ---------------------------------------------------------------------------
extern "C" void kernel_launch(void* const* d_in, const int* in_sizes, int n_in,
                              void* d_out, int out_size) {
    const float* x     = (const float*)d_in[0];
    const int*   ei    = (const int*)  d_in[1];
    const float* ew    = (const float*)d_in[2];
    const int*   ptei  = (const int*)  d_in[3];
    const float* pt    = (const float*)d_in[4];
    const float* alpha = (const float*)d_in[5];
    const float* gamma = (const float*)d_in[6];
    (void)in_sizes; (void)n_in; (void)out_size; (void)ew;

    float* out       = (float*)d_out;
    float* loss_slot = out + (size_t)NN * DD;
    float* w_out     = loss_slot + 1;

    k_init<<<(NN * DD + 255) / 256, 256>>>(loss_slot);
    k_deg<<<(EE + 255) / 256, 256>>>(ei);
    k_dis<<<(NN + 255) / 256, 256>>>();
    k_agg<<<(int)(((long long)EE * 32 + 255) / 256), 256>>>(ei, ew, x);
    k_pnorm<<<(PP * 32 + 255) / 256, 256>>>(pt);
    k_xstruct<<<(int)(((long long)NN * 32 + 255) / 256), 256>>>(x, gamma);
    k_kbuild<<<(NN + 63) / 64, 256>>>();
    for (int it = 1; it <= 19; it++) k_sink<<<592, 256>>>(it);
    k_epi<<<1184, 128>>>(x, pt, alpha, out, loss_slot);
    k_w<<<1184, 128>>>(ptei, w_out);
    k_wnorm<<<(EPTN + 255) / 256, 256>>>(w_out);
}

// round 2
// speedup vs baseline: 1.2968x; 1.2968x over previous
#include <cuda_runtime.h>

#define NN   100000
#define DD   128
#define PP   64
#define EE   3200000
#define EPTN 5000000
#define EPSI 0.1f
#define INVN (1.0f/100000.0f)
#define BV   (1.0f/64.0f)

// -------- scratch (device globals; no dynamic allocation allowed) ----------
__device__ float g_deg[NN];
__device__ float g_dis[NN];
__device__ float g_xaggr[NN*DD];
__device__ float g_xs[NN*DD];
__device__ float g_pn[PP*DD];
__device__ float g_K[(size_t)NN*PP];
__device__ float g_t[21*PP];
__device__ float g_xf[NN*DD];
__device__ unsigned int g_wmax;
// CSR scratch
__device__ int   g_rowcnt[NN];
__device__ int   g_rowstart[NN+1];
__device__ int   g_cursor[NN];
__device__ int   g_csr_col[EE];
__device__ float g_csr_w[EE];

__device__ __forceinline__ float warp_sum(float v) {
    v += __shfl_xor_sync(0xffffffffu, v, 16);
    v += __shfl_xor_sync(0xffffffffu, v, 8);
    v += __shfl_xor_sync(0xffffffffu, v, 4);
    v += __shfl_xor_sync(0xffffffffu, v, 2);
    v += __shfl_xor_sync(0xffffffffu, v, 1);
    return v;
}

// ---------------------------------------------------------------------------
__global__ void k_init(float* loss_slot) {
    int idx = blockIdx.x * blockDim.x + threadIdx.x;
    if (idx < NN) { g_deg[idx] = 0.f; g_rowcnt[idx] = 0; }
    if (idx < 21*PP) g_t[idx] = 0.f;
    if (idx == 0) { g_wmax = 0u; *loss_slot = 0.f; }
}

// degree of col (float) + count of row (int) in one pass
__global__ void k_deg(const int* __restrict__ ei) {
    int e = blockIdx.x * blockDim.x + threadIdx.x;
    if (e < EE) {
        atomicAdd(&g_deg[ei[EE + e]], 1.0f);
        atomicAdd(&g_rowcnt[ei[e]], 1);
    }
}

__global__ void k_dis() {
    int i = blockIdx.x * blockDim.x + threadIdx.x;
    if (i < NN) {
        float d = g_deg[i];
        g_dis[i] = (d > 0.f) ? rsqrtf(d) : 0.f;
    }
}

// single-block exclusive prefix scan of g_rowcnt -> g_rowstart, g_cursor
__global__ void k_scan() {
    __shared__ int wsum[32];
    __shared__ int sbase;
    int tid = threadIdx.x, lane = tid & 31, w = tid >> 5;
    if (tid == 0) sbase = 0;
    __syncthreads();
    for (int chunk = 0; chunk < NN; chunk += 1024) {
        int i = chunk + tid;
        int v = (i < NN) ? g_rowcnt[i] : 0;
        int s = v;
#pragma unroll
        for (int off = 1; off < 32; off <<= 1) {
            int n = __shfl_up_sync(0xffffffffu, s, off);
            if (lane >= off) s += n;
        }
        if (lane == 31) wsum[w] = s;
        __syncthreads();
        if (w == 0) {
            int t  = wsum[lane];
            int ts = t;
#pragma unroll
            for (int off = 1; off < 32; off <<= 1) {
                int n = __shfl_up_sync(0xffffffffu, ts, off);
                if (lane >= off) ts += n;
            }
            wsum[lane] = ts - t;   // exclusive prefix of warp sums
        }
        __syncthreads();
        int excl = sbase + wsum[w] + s - v;
        if (i < NN) { g_rowstart[i] = excl; g_cursor[i] = excl; }
        __syncthreads();
        if (tid == 1023) sbase += wsum[31] + s;
        __syncthreads();
    }
    if (threadIdx.x == 0) g_rowstart[NN] = EE;
}

// scatter edges into CSR with precomputed normalized weight
__global__ void k_scatter(const int* __restrict__ ei, const float* __restrict__ ew) {
    int e = blockIdx.x * blockDim.x + threadIdx.x;
    if (e >= EE) return;
    int r = ei[e];
    int c = ei[EE + e];
    float nw = g_dis[r] * ew[e] * g_dis[c];
    int pos = atomicAdd(&g_cursor[r], 1);
    g_csr_col[pos] = c;
    g_csr_w[pos]   = nw;
}

// warp per row: register accumulation, single store per row. No atomics.
__global__ void k_aggcsr(const float* __restrict__ x) {
    int tid = threadIdx.x;
    int lane = tid & 31;
    int warpId = (blockIdx.x * blockDim.x + tid) >> 5;
    int nW = (gridDim.x * blockDim.x) >> 5;
    for (int r = warpId; r < NN; r += nW) {
        int s = g_rowstart[r], e = g_rowstart[r + 1];
        float4 acc = make_float4(0.f, 0.f, 0.f, 0.f);
        for (int base = s; base < e; base += 32) {
            int j = base + lane;
            int cj = 0; float wj = 0.f;
            if (j < e) { cj = g_csr_col[j]; wj = g_csr_w[j]; }
            int cnt = min(32, e - base);
            for (int k = 0; k < cnt; k++) {
                int   ck = __shfl_sync(0xffffffffu, cj, k);
                float wk = __shfl_sync(0xffffffffu, wj, k);
                float4 v = *(const float4*)(x + (size_t)ck * DD + lane * 4);
                acc.x += wk * v.x;
                acc.y += wk * v.y;
                acc.z += wk * v.z;
                acc.w += wk * v.w;
            }
        }
        *(float4*)(g_xaggr + (size_t)r * DD + lane * 4) = acc;
    }
}

// normalize prompt tokens (warp per prompt)
__global__ void k_pnorm(const float* __restrict__ pt) {
    int t = blockIdx.x * blockDim.x + threadIdx.x;
    int p = t >> 5, lane = t & 31;
    if (p >= PP) return;
    float4 v = *(const float4*)(pt + (size_t)p * DD + lane * 4);
    float ss = warp_sum(v.x*v.x + v.y*v.y + v.z*v.z + v.w*v.w);
    float inv = 1.f / fmaxf(sqrtf(ss), 1e-12f);
    float4 o = make_float4(v.x*inv, v.y*inv, v.z*inv, v.w*inv);
    *(float4*)(g_pn + (size_t)p * DD + lane * 4) = o;
}

// x_struct = (1-g)x + g*x_aggr, l2-normalized -> g_xs  (warp per row)
__global__ void k_xstruct(const float* __restrict__ x, const float* __restrict__ gamma_p) {
    int t = blockIdx.x * blockDim.x + threadIdx.x;
    int r = t >> 5, lane = t & 31;
    if (r >= NN) return;
    float g = *gamma_p;
    float4 xv = *(const float4*)(x       + (size_t)r * DD + lane * 4);
    float4 av = *(const float4*)(g_xaggr + (size_t)r * DD + lane * 4);
    float4 s;
    s.x = (1.f - g) * xv.x + g * av.x;
    s.y = (1.f - g) * xv.y + g * av.y;
    s.z = (1.f - g) * xv.z + g * av.z;
    s.w = (1.f - g) * xv.w + g * av.w;
    float ss = warp_sum(s.x*s.x + s.y*s.y + s.z*s.z + s.w*s.w);
    float inv = 1.f / fmaxf(sqrtf(ss), 1e-12f);
    float4 o = make_float4(s.x*inv, s.y*inv, s.z*inv, s.w*inv);
    *(float4*)(g_xs + (size_t)r * DD + lane * 4) = o;
}

// K[i][p] = exp(10*(cos-1)); also t0[p] = (1/N) * sum_i K[i][p]
__global__ void k_kbuild() {
    __shared__ float xs_sh[64][68];
    __shared__ float pn_sh[64][68];
    __shared__ float t_sh[PP];
    int tid = threadIdx.x;
    int tx = tid & 15;
    int ty = tid >> 4;
    int rowBase = blockIdx.x * 64;

    float acc[4][4];
#pragma unroll
    for (int i = 0; i < 4; i++)
#pragma unroll
        for (int j = 0; j < 4; j++) acc[i][j] = 0.f;

    for (int ch = 0; ch < 2; ch++) {
#pragma unroll
        for (int i = 0; i < 4; i++) {
            int rr = ty + i * 16;
            int c4 = tx * 4;
            int gr = rowBase + rr;
            float4 v = (gr < NN) ? *(const float4*)(g_xs + (size_t)gr * DD + ch * 64 + c4)
                                 : make_float4(0.f, 0.f, 0.f, 0.f);
            *(float4*)&xs_sh[rr][c4] = v;
            *(float4*)&pn_sh[rr][c4] = *(const float4*)(g_pn + (size_t)rr * DD + ch * 64 + c4);
        }
        __syncthreads();
#pragma unroll 8
        for (int d = 0; d < 64; d += 4) {
            float4 a[4], b[4];
#pragma unroll
            for (int i = 0; i < 4; i++) a[i] = *(float4*)&xs_sh[ty * 4 + i][d];
#pragma unroll
            for (int j = 0; j < 4; j++) b[j] = *(float4*)&pn_sh[tx * 4 + j][d];
#pragma unroll
            for (int i = 0; i < 4; i++)
#pragma unroll
                for (int j = 0; j < 4; j++) {
                    acc[i][j] += a[i].x * b[j].x;
                    acc[i][j] += a[i].y * b[j].y;
                    acc[i][j] += a[i].z * b[j].z;
                    acc[i][j] += a[i].w * b[j].w;
                }
        }
        __syncthreads();
    }

    if (tid < PP) t_sh[tid] = 0.f;
    __syncthreads();

    float colsum[4] = {0.f, 0.f, 0.f, 0.f};
#pragma unroll
    for (int i = 0; i < 4; i++) {
        int gr = rowBase + ty * 4 + i;
        if (gr < NN) {
            float4 kv;
            kv.x = __expf(10.f * (acc[i][0] - 1.f));
            kv.y = __expf(10.f * (acc[i][1] - 1.f));
            kv.z = __expf(10.f * (acc[i][2] - 1.f));
            kv.w = __expf(10.f * (acc[i][3] - 1.f));
            *(float4*)(g_K + (size_t)gr * PP + tx * 4) = kv;
            colsum[0] += kv.x; colsum[1] += kv.y; colsum[2] += kv.z; colsum[3] += kv.w;
        }
    }
#pragma unroll
    for (int j = 0; j < 4; j++) atomicAdd(&t_sh[tx * 4 + j], colsum[j]);
    __syncthreads();
    if (tid < PP) atomicAdd(&g_t[tid], t_sh[tid] * INVN);
}

// one Sinkhorn iteration
__global__ void k_sink(int iter) {
    __shared__ float v_sh[PP];
    int tid = threadIdx.x;
    if (tid < PP) v_sh[tid] = BV / (g_t[(iter - 1) * PP + tid] + 1e-30f);
    __syncthreads();
    int lane = tid & 31;
    int warpId = (blockIdx.x * blockDim.x + tid) >> 5;
    int nW = (gridDim.x * blockDim.x) >> 5;
    float v0 = v_sh[2 * lane], v1 = v_sh[2 * lane + 1];
    float a0 = 0.f, a1 = 0.f;
    for (int r = warpId; r < NN; r += nW) {
        float2 k2 = *(const float2*)(g_K + (size_t)r * PP + 2 * lane);
        float s = warp_sum(k2.x * v0 + k2.y * v1);
        float u = INVN / (s + 1e-30f);
        a0 += k2.x * u;
        a1 += k2.y * u;
    }
    atomicAdd(&g_t[iter * PP + 2 * lane],     a0);
    atomicAdd(&g_t[iter * PP + 2 * lane + 1], a1);
}

// epilogue: T*, ot_loss, prompt_message, x_adapted, xf
__global__ void k_epi(const float* __restrict__ x, const float* __restrict__ pt,
                      const float* __restrict__ alpha_p,
                      float* __restrict__ out_x, float* __restrict__ loss_out) {
    __shared__ float pt_sh[PP][DD];
    __shared__ float T_sh[4][8][PP];
    __shared__ float v_sh[PP];
    int tid = threadIdx.x;
    for (int i = tid; i < PP * DD / 4; i += blockDim.x)
        ((float4*)&pt_sh[0][0])[i] = ((const float4*)pt)[i];
    if (tid < PP) v_sh[tid] = BV / (g_t[19 * PP + tid] + 1e-30f);
    __syncthreads();

    int lane = tid & 31, w = tid >> 5;
    int warpId = (blockIdx.x * blockDim.x + tid) >> 5;
    int nW = (gridDim.x * blockDim.x) >> 5;
    float v0 = v_sh[2 * lane], v1 = v_sh[2 * lane + 1];
    float scaleA = (*alpha_p) * (float)NN;
    float lossAcc = 0.f;

    for (int base = warpId * 8; base < NN; base += nW * 8) {
#pragma unroll
        for (int rr = 0; rr < 8; rr++) {
            int r = base + rr;
            float2 k2 = *(const float2*)(g_K + (size_t)r * PP + 2 * lane);
            float s = warp_sum(k2.x * v0 + k2.y * v1);
            float u = INVN / (s + 1e-30f);
            float T0 = u * k2.x * v0;
            float T1 = u * k2.y * v1;
            lossAcc += T0 * (-EPSI * __logf(k2.x)) + T1 * (-EPSI * __logf(k2.y));
            T_sh[w][rr][2 * lane]     = T0;
            T_sh[w][rr][2 * lane + 1] = T1;
        }
        __syncwarp();
        float4 pm[8];
#pragma unroll
        for (int rr = 0; rr < 8; rr++) pm[rr] = make_float4(0.f, 0.f, 0.f, 0.f);
#pragma unroll 4
        for (int p = 0; p < PP; p++) {
            float4 pv = *(const float4*)&pt_sh[p][lane * 4];
#pragma unroll
            for (int rr = 0; rr < 8; rr++) {
                float tp = T_sh[w][rr][p];
                pm[rr].x += tp * pv.x;
                pm[rr].y += tp * pv.y;
                pm[rr].z += tp * pv.z;
                pm[rr].w += tp * pv.w;
            }
        }
#pragma unroll
        for (int rr = 0; rr < 8; rr++) {
            int r = base + rr;
            float4 xv = *(const float4*)(x + (size_t)r * DD + lane * 4);
            float4 o;
            o.x = xv.x + scaleA * pm[rr].x;
            o.y = xv.y + scaleA * pm[rr].y;
            o.z = xv.z + scaleA * pm[rr].z;
            o.w = xv.w + scaleA * pm[rr].w;
            *(float4*)(out_x + (size_t)r * DD + lane * 4) = o;
            float ss = warp_sum(o.x*o.x + o.y*o.y + o.z*o.z + o.w*o.w);
            float inv = 1.f / fmaxf(sqrtf(ss), 1e-12f);
            float4 f = make_float4(o.x*inv, o.y*inv, o.z*inv, o.w*inv);
            *(float4*)(g_xf + (size_t)r * DD + lane * 4) = f;
        }
        __syncwarp();
    }
    lossAcc = warp_sum(lossAcc);
    if (lane == 0) atomicAdd(loss_out, lossAcc);
}

// w_e = relu(dot(xf[r], xf[c])); warp per edge, 2 edges in flight
__global__ void k_w(const int* __restrict__ ptei, float* __restrict__ w_out) {
    int tid = threadIdx.x;
    int lane = tid & 31;
    int warpId = (blockIdx.x * blockDim.x + tid) >> 5;
    int nW = (gridDim.x * blockDim.x) >> 5;
    float wmax = 0.f;
    for (int base = warpId * 2; base < EPTN; base += nW * 2) {
        int e0 = base, e1 = base + 1;   // EPTN even, base even -> e1 < EPTN
        int r0 = __ldg(&ptei[e0]);
        int c0 = __ldg(&ptei[EPTN + e0]);
        int r1 = __ldg(&ptei[e1]);
        int c1 = __ldg(&ptei[EPTN + e1]);
        float4 a0 = *(const float4*)(g_xf + (size_t)r0 * DD + lane * 4);
        float4 b0 = *(const float4*)(g_xf + (size_t)c0 * DD + lane * 4);
        float4 a1 = *(const float4*)(g_xf + (size_t)r1 * DD + lane * 4);
        float4 b1 = *(const float4*)(g_xf + (size_t)c1 * DD + lane * 4);
        float d0 = a0.x*b0.x + a0.y*b0.y + a0.z*b0.z + a0.w*b0.w;
        float d1 = a1.x*b1.x + a1.y*b1.y + a1.z*b1.z + a1.w*b1.w;
        d0 = warp_sum(d0);
        d1 = warp_sum(d1);
        d0 = fmaxf(d0, 0.f);
        d1 = fmaxf(d1, 0.f);
        if (lane == 0) w_out[e0] = d0;
        if (lane == 1) w_out[e1] = d1;
        wmax = fmaxf(wmax, fmaxf(d0, d1));
    }
    wmax = fmaxf(wmax, __shfl_xor_sync(0xffffffffu, wmax, 16));
    wmax = fmaxf(wmax, __shfl_xor_sync(0xffffffffu, wmax, 8));
    wmax = fmaxf(wmax, __shfl_xor_sync(0xffffffffu, wmax, 4));
    wmax = fmaxf(wmax, __shfl_xor_sync(0xffffffffu, wmax, 2));
    wmax = fmaxf(wmax, __shfl_xor_sync(0xffffffffu, wmax, 1));
    if (lane == 0) atomicMax(&g_wmax, __float_as_uint(wmax));
}

__global__ void k_wnorm(float* __restrict__ w_out) {
    int i = blockIdx.x * blockDim.x + threadIdx.x;
    if (i < EPTN) {
        float sc = 1.f / (__uint_as_float(g_wmax) + 1e-8f);
        w_out[i] *= sc;
    }
}

// ---------------------------------------------------------------------------
extern "C" void kernel_launch(void* const* d_in, const int* in_sizes, int n_in,
                              void* d_out, int out_size) {
    const float* x     = (const float*)d_in[0];
    const int*   ei    = (const int*)  d_in[1];
    const float* ew    = (const float*)d_in[2];
    const int*   ptei  = (const int*)  d_in[3];
    const float* pt    = (const float*)d_in[4];
    const float* alpha = (const float*)d_in[5];
    const float* gamma = (const float*)d_in[6];
    (void)in_sizes; (void)n_in; (void)out_size;

    float* out       = (float*)d_out;
    float* loss_slot = out + (size_t)NN * DD;
    float* w_out     = loss_slot + 1;

    k_init<<<(NN + 255) / 256, 256>>>(loss_slot);
    k_deg<<<(EE + 255) / 256, 256>>>(ei);
    k_dis<<<(NN + 255) / 256, 256>>>();
    k_scan<<<1, 1024>>>();
    k_scatter<<<(EE + 255) / 256, 256>>>(ei, ew);
    k_aggcsr<<<1184, 256>>>(x);
    k_pnorm<<<(PP * 32 + 255) / 256, 256>>>(pt);
    k_xstruct<<<(int)(((long long)NN * 32 + 255) / 256), 256>>>(x, gamma);
    k_kbuild<<<(NN + 63) / 64, 256>>>();
    for (int it = 1; it <= 19; it++) k_sink<<<592, 256>>>(it);
    k_epi<<<1184, 128>>>(x, pt, alpha, out, loss_slot);
    k_w<<<1184, 256>>>(ptei, w_out);
    k_wnorm<<<(EPTN + 255) / 256, 256>>>(w_out);
}

// round 3
// speedup vs baseline: 1.3977x; 1.0778x over previous
#include <cuda_runtime.h>
#include <cuda_fp16.h>

#define NN   100000
#define DD   128
#define PP   64
#define EE   3200000
#define EPTN 5000000
#define EPSI 0.1f
#define INVN (1.0f/100000.0f)
#define BV   (1.0f/64.0f)
#define SCAN_BLOCKS 98   // ceil(100000/1024)

// -------- scratch (device globals; no dynamic allocation allowed) ----------
__device__ float g_deg[NN];
__device__ float g_dis[NN];
__device__ float g_xaggr[NN*DD];
__device__ float g_xs[NN*DD];
__device__ float g_pn[PP*DD];
__device__ float g_K[(size_t)NN*PP];
__device__ float g_t[21*PP];
__device__ __half g_xfh[NN*DD];
__device__ unsigned int g_wmax;
// CSR scratch
__device__ int   g_rowcnt[NN];
__device__ int   g_rowstart[NN+1];
__device__ int   g_cursor[NN];
__device__ int   g_csr_col[EE];
__device__ float g_csr_w[EE];
__device__ int   g_bsum[SCAN_BLOCKS];

__device__ __forceinline__ float warp_sum(float v) {
    v += __shfl_xor_sync(0xffffffffu, v, 16);
    v += __shfl_xor_sync(0xffffffffu, v, 8);
    v += __shfl_xor_sync(0xffffffffu, v, 4);
    v += __shfl_xor_sync(0xffffffffu, v, 2);
    v += __shfl_xor_sync(0xffffffffu, v, 1);
    return v;
}

// ---------------------------------------------------------------------------
__global__ void k_init(float* loss_slot) {
    int idx = blockIdx.x * blockDim.x + threadIdx.x;
    if (idx < NN) { g_deg[idx] = 0.f; g_rowcnt[idx] = 0; }
    if (idx < 21*PP) g_t[idx] = 0.f;
    if (idx == 0) { g_wmax = 0u; *loss_slot = 0.f; }
}

// degree of col (float) + count of row (int) in one pass
__global__ void k_deg(const int* __restrict__ ei) {
    int e = blockIdx.x * blockDim.x + threadIdx.x;
    if (e < EE) {
        atomicAdd(&g_deg[ei[EE + e]], 1.0f);
        atomicAdd(&g_rowcnt[ei[e]], 1);
    }
}

__global__ void k_dis() {
    int i = blockIdx.x * blockDim.x + threadIdx.x;
    if (i < NN) {
        float d = g_deg[i];
        g_dis[i] = (d > 0.f) ? rsqrtf(d) : 0.f;
    }
}

// ---- parallel scan: per-block scan, block-sum scan, offset add ------------
__global__ void k_scanA() {
    __shared__ int wsum[32];
    int tid = threadIdx.x, lane = tid & 31, w = tid >> 5;
    int i = blockIdx.x * 1024 + tid;
    int v = (i < NN) ? g_rowcnt[i] : 0;
    int s = v;
#pragma unroll
    for (int off = 1; off < 32; off <<= 1) {
        int n = __shfl_up_sync(0xffffffffu, s, off);
        if (lane >= off) s += n;
    }
    if (lane == 31) wsum[w] = s;
    __syncthreads();
    if (w == 0) {
        int t  = wsum[lane];
        int ts = t;
#pragma unroll
        for (int off = 1; off < 32; off <<= 1) {
            int n = __shfl_up_sync(0xffffffffu, ts, off);
            if (lane >= off) ts += n;
        }
        wsum[lane] = ts - t;   // exclusive prefix of warp sums
    }
    __syncthreads();
    int excl = wsum[w] + s - v;   // block-local exclusive
    if (i < NN) g_rowstart[i] = excl;
    if (tid == 1023) g_bsum[blockIdx.x] = excl + v;   // block total
}

__global__ void k_scanB() {
    // serial exclusive scan of 98 block sums (tiny)
    if (threadIdx.x == 0) {
        int acc = 0;
        for (int b = 0; b < SCAN_BLOCKS; b++) {
            int t = g_bsum[b];
            g_bsum[b] = acc;
            acc += t;
        }
    }
}

__global__ void k_scanC() {
    int i = blockIdx.x * 1024 + threadIdx.x;
    if (i < NN) {
        int v = g_rowstart[i] + g_bsum[blockIdx.x];
        g_rowstart[i] = v;
        g_cursor[i]   = v;
    }
    if (i == 0) g_rowstart[NN] = EE;
}

// scatter edges into CSR with precomputed normalized weight
__global__ void k_scatter(const int* __restrict__ ei, const float* __restrict__ ew) {
    int e = blockIdx.x * blockDim.x + threadIdx.x;
    if (e >= EE) return;
    int r = ei[e];
    int c = ei[EE + e];
    float nw = g_dis[r] * ew[e] * g_dis[c];
    int pos = atomicAdd(&g_cursor[r], 1);
    g_csr_col[pos] = c;
    g_csr_w[pos]   = nw;
}

// warp per row: register accumulation, single store per row. No atomics.
__global__ void k_aggcsr(const float* __restrict__ x) {
    int tid = threadIdx.x;
    int lane = tid & 31;
    int warpId = (blockIdx.x * blockDim.x + tid) >> 5;
    int nW = (gridDim.x * blockDim.x) >> 5;
    for (int r = warpId; r < NN; r += nW) {
        int s = g_rowstart[r], e = g_rowstart[r + 1];
        float4 acc = make_float4(0.f, 0.f, 0.f, 0.f);
        for (int base = s; base < e; base += 32) {
            int j = base + lane;
            int cj = 0; float wj = 0.f;
            if (j < e) { cj = g_csr_col[j]; wj = g_csr_w[j]; }
            int cnt = min(32, e - base);
            for (int k = 0; k < cnt; k++) {
                int   ck = __shfl_sync(0xffffffffu, cj, k);
                float wk = __shfl_sync(0xffffffffu, wj, k);
                float4 v = *(const float4*)(x + (size_t)ck * DD + lane * 4);
                acc.x += wk * v.x;
                acc.y += wk * v.y;
                acc.z += wk * v.z;
                acc.w += wk * v.w;
            }
        }
        *(float4*)(g_xaggr + (size_t)r * DD + lane * 4) = acc;
    }
}

// normalize prompt tokens (warp per prompt)
__global__ void k_pnorm(const float* __restrict__ pt) {
    int t = blockIdx.x * blockDim.x + threadIdx.x;
    int p = t >> 5, lane = t & 31;
    if (p >= PP) return;
    float4 v = *(const float4*)(pt + (size_t)p * DD + lane * 4);
    float ss = warp_sum(v.x*v.x + v.y*v.y + v.z*v.z + v.w*v.w);
    float inv = 1.f / fmaxf(sqrtf(ss), 1e-12f);
    float4 o = make_float4(v.x*inv, v.y*inv, v.z*inv, v.w*inv);
    *(float4*)(g_pn + (size_t)p * DD + lane * 4) = o;
}

// x_struct = (1-g)x + g*x_aggr, l2-normalized -> g_xs  (warp per row)
__global__ void k_xstruct(const float* __restrict__ x, const float* __restrict__ gamma_p) {
    int t = blockIdx.x * blockDim.x + threadIdx.x;
    int r = t >> 5, lane = t & 31;
    if (r >= NN) return;
    float g = *gamma_p;
    float4 xv = *(const float4*)(x       + (size_t)r * DD + lane * 4);
    float4 av = *(const float4*)(g_xaggr + (size_t)r * DD + lane * 4);
    float4 s;
    s.x = (1.f - g) * xv.x + g * av.x;
    s.y = (1.f - g) * xv.y + g * av.y;
    s.z = (1.f - g) * xv.z + g * av.z;
    s.w = (1.f - g) * xv.w + g * av.w;
    float ss = warp_sum(s.x*s.x + s.y*s.y + s.z*s.z + s.w*s.w);
    float inv = 1.f / fmaxf(sqrtf(ss), 1e-12f);
    float4 o = make_float4(s.x*inv, s.y*inv, s.z*inv, s.w*inv);
    *(float4*)(g_xs + (size_t)r * DD + lane * 4) = o;
}

// K[i][p] = exp(10*(cos-1)); also t0[p] = (1/N) * sum_i K[i][p]
__global__ void k_kbuild() {
    __shared__ float xs_sh[64][68];
    __shared__ float pn_sh[64][68];
    __shared__ float t_sh[PP];
    int tid = threadIdx.x;
    int tx = tid & 15;
    int ty = tid >> 4;
    int rowBase = blockIdx.x * 64;

    float acc[4][4];
#pragma unroll
    for (int i = 0; i < 4; i++)
#pragma unroll
        for (int j = 0; j < 4; j++) acc[i][j] = 0.f;

    for (int ch = 0; ch < 2; ch++) {
#pragma unroll
        for (int i = 0; i < 4; i++) {
            int rr = ty + i * 16;
            int c4 = tx * 4;
            int gr = rowBase + rr;
            float4 v = (gr < NN) ? *(const float4*)(g_xs + (size_t)gr * DD + ch * 64 + c4)
                                 : make_float4(0.f, 0.f, 0.f, 0.f);
            *(float4*)&xs_sh[rr][c4] = v;
            *(float4*)&pn_sh[rr][c4] = *(const float4*)(g_pn + (size_t)rr * DD + ch * 64 + c4);
        }
        __syncthreads();
#pragma unroll 8
        for (int d = 0; d < 64; d += 4) {
            float4 a[4], b[4];
#pragma unroll
            for (int i = 0; i < 4; i++) a[i] = *(float4*)&xs_sh[ty * 4 + i][d];
#pragma unroll
            for (int j = 0; j < 4; j++) b[j] = *(float4*)&pn_sh[tx * 4 + j][d];
#pragma unroll
            for (int i = 0; i < 4; i++)
#pragma unroll
                for (int j = 0; j < 4; j++) {
                    acc[i][j] += a[i].x * b[j].x;
                    acc[i][j] += a[i].y * b[j].y;
                    acc[i][j] += a[i].z * b[j].z;
                    acc[i][j] += a[i].w * b[j].w;
                }
        }
        __syncthreads();
    }

    if (tid < PP) t_sh[tid] = 0.f;
    __syncthreads();

    float colsum[4] = {0.f, 0.f, 0.f, 0.f};
#pragma unroll
    for (int i = 0; i < 4; i++) {
        int gr = rowBase + ty * 4 + i;
        if (gr < NN) {
            float4 kv;
            kv.x = __expf(10.f * (acc[i][0] - 1.f));
            kv.y = __expf(10.f * (acc[i][1] - 1.f));
            kv.z = __expf(10.f * (acc[i][2] - 1.f));
            kv.w = __expf(10.f * (acc[i][3] - 1.f));
            *(float4*)(g_K + (size_t)gr * PP + tx * 4) = kv;
            colsum[0] += kv.x; colsum[1] += kv.y; colsum[2] += kv.z; colsum[3] += kv.w;
        }
    }
#pragma unroll
    for (int j = 0; j < 4; j++) atomicAdd(&t_sh[tx * 4 + j], colsum[j]);
    __syncthreads();
    if (tid < PP) atomicAdd(&g_t[tid], t_sh[tid] * INVN);
}

// one Sinkhorn iteration
__global__ void k_sink(int iter) {
    __shared__ float v_sh[PP];
    int tid = threadIdx.x;
    if (tid < PP) v_sh[tid] = BV / (g_t[(iter - 1) * PP + tid] + 1e-30f);
    __syncthreads();
    int lane = tid & 31;
    int warpId = (blockIdx.x * blockDim.x + tid) >> 5;
    int nW = (gridDim.x * blockDim.x) >> 5;
    float v0 = v_sh[2 * lane], v1 = v_sh[2 * lane + 1];
    float a0 = 0.f, a1 = 0.f;
    for (int r = warpId; r < NN; r += nW) {
        float2 k2 = *(const float2*)(g_K + (size_t)r * PP + 2 * lane);
        float s = warp_sum(k2.x * v0 + k2.y * v1);
        float u = INVN / (s + 1e-30f);
        a0 += k2.x * u;
        a1 += k2.y * u;
    }
    atomicAdd(&g_t[iter * PP + 2 * lane],     a0);
    atomicAdd(&g_t[iter * PP + 2 * lane + 1], a1);
}

// epilogue: T*, ot_loss, prompt_message, x_adapted, xf (fp16)
__global__ void k_epi(const float* __restrict__ x, const float* __restrict__ pt,
                      const float* __restrict__ alpha_p,
                      float* __restrict__ out_x, float* __restrict__ loss_out) {
    __shared__ float pt_sh[PP][DD];
    __shared__ float T_sh[4][8][PP];
    __shared__ float v_sh[PP];
    int tid = threadIdx.x;
    for (int i = tid; i < PP * DD / 4; i += blockDim.x)
        ((float4*)&pt_sh[0][0])[i] = ((const float4*)pt)[i];
    if (tid < PP) v_sh[tid] = BV / (g_t[19 * PP + tid] + 1e-30f);
    __syncthreads();

    int lane = tid & 31, w = tid >> 5;
    int warpId = (blockIdx.x * blockDim.x + tid) >> 5;
    int nW = (gridDim.x * blockDim.x) >> 5;
    float v0 = v_sh[2 * lane], v1 = v_sh[2 * lane + 1];
    float scaleA = (*alpha_p) * (float)NN;
    float lossAcc = 0.f;

    for (int base = warpId * 8; base < NN; base += nW * 8) {
#pragma unroll
        for (int rr = 0; rr < 8; rr++) {
            int r = base + rr;
            float2 k2 = *(const float2*)(g_K + (size_t)r * PP + 2 * lane);
            float s = warp_sum(k2.x * v0 + k2.y * v1);
            float u = INVN / (s + 1e-30f);
            float T0 = u * k2.x * v0;
            float T1 = u * k2.y * v1;
            lossAcc += T0 * (-EPSI * __logf(k2.x)) + T1 * (-EPSI * __logf(k2.y));
            T_sh[w][rr][2 * lane]     = T0;
            T_sh[w][rr][2 * lane + 1] = T1;
        }
        __syncwarp();
        float4 pm[8];
#pragma unroll
        for (int rr = 0; rr < 8; rr++) pm[rr] = make_float4(0.f, 0.f, 0.f, 0.f);
#pragma unroll 4
        for (int p = 0; p < PP; p++) {
            float4 pv = *(const float4*)&pt_sh[p][lane * 4];
#pragma unroll
            for (int rr = 0; rr < 8; rr++) {
                float tp = T_sh[w][rr][p];
                pm[rr].x += tp * pv.x;
                pm[rr].y += tp * pv.y;
                pm[rr].z += tp * pv.z;
                pm[rr].w += tp * pv.w;
            }
        }
#pragma unroll
        for (int rr = 0; rr < 8; rr++) {
            int r = base + rr;
            float4 xv = *(const float4*)(x + (size_t)r * DD + lane * 4);
            float4 o;
            o.x = xv.x + scaleA * pm[rr].x;
            o.y = xv.y + scaleA * pm[rr].y;
            o.z = xv.z + scaleA * pm[rr].z;
            o.w = xv.w + scaleA * pm[rr].w;
            *(float4*)(out_x + (size_t)r * DD + lane * 4) = o;
            float ss = warp_sum(o.x*o.x + o.y*o.y + o.z*o.z + o.w*o.w);
            float inv = 1.f / fmaxf(sqrtf(ss), 1e-12f);
            __half2 h0 = __floats2half2_rn(o.x * inv, o.y * inv);
            __half2 h1 = __floats2half2_rn(o.z * inv, o.w * inv);
            __half2* dst = (__half2*)(g_xfh + (size_t)r * DD + lane * 4);
            uint2 packed;
            packed.x = *(unsigned int*)&h0;
            packed.y = *(unsigned int*)&h1;
            *(uint2*)dst = packed;
        }
        __syncwarp();
    }
    lossAcc = warp_sum(lossAcc);
    if (lane == 0) atomicAdd(loss_out, lossAcc);
}

// w_e = relu(dot(xf[r], xf[c])); warp per edge, 4 edges in flight, fp16 gathers
__global__ void k_w(const int* __restrict__ ptei, float* __restrict__ w_out) {
    int tid = threadIdx.x;
    int lane = tid & 31;
    int warpId = (blockIdx.x * blockDim.x + tid) >> 5;
    int nW = (gridDim.x * blockDim.x) >> 5;
    float wmax = 0.f;
    for (int base = warpId * 4; base < EPTN; base += nW * 4) {
        int r[4], c[4];
#pragma unroll
        for (int q = 0; q < 4; q++) {
            r[q] = __ldg(&ptei[base + q]);
            c[q] = __ldg(&ptei[EPTN + base + q]);
        }
        float d[4];
#pragma unroll
        for (int q = 0; q < 4; q++) {
            uint2 ap = *(const uint2*)(g_xfh + (size_t)r[q] * DD + lane * 4);
            uint2 bp = *(const uint2*)(g_xfh + (size_t)c[q] * DD + lane * 4);
            float2 a0 = __half22float2(*(__half2*)&ap.x);
            float2 a1 = __half22float2(*(__half2*)&ap.y);
            float2 b0 = __half22float2(*(__half2*)&bp.x);
            float2 b1 = __half22float2(*(__half2*)&bp.y);
            d[q] = a0.x*b0.x + a0.y*b0.y + a1.x*b1.x + a1.y*b1.y;
        }
#pragma unroll
        for (int q = 0; q < 4; q++) {
            d[q] = warp_sum(d[q]);
            d[q] = fmaxf(d[q], 0.f);
            wmax = fmaxf(wmax, d[q]);
        }
        if (lane < 4) w_out[base + lane] = d[lane];
    }
    wmax = fmaxf(wmax, __shfl_xor_sync(0xffffffffu, wmax, 16));
    wmax = fmaxf(wmax, __shfl_xor_sync(0xffffffffu, wmax, 8));
    wmax = fmaxf(wmax, __shfl_xor_sync(0xffffffffu, wmax, 4));
    wmax = fmaxf(wmax, __shfl_xor_sync(0xffffffffu, wmax, 2));
    wmax = fmaxf(wmax, __shfl_xor_sync(0xffffffffu, wmax, 1));
    if (lane == 0) atomicMax(&g_wmax, __float_as_uint(wmax));
}

__global__ void k_wnorm(float* __restrict__ w_out) {
    int i = blockIdx.x * blockDim.x + threadIdx.x;
    if (i < EPTN) {
        float sc = 1.f / (__uint_as_float(g_wmax) + 1e-8f);
        w_out[i] *= sc;
    }
}

// ---------------------------------------------------------------------------
extern "C" void kernel_launch(void* const* d_in, const int* in_sizes, int n_in,
                              void* d_out, int out_size) {
    const float* x     = (const float*)d_in[0];
    const int*   ei    = (const int*)  d_in[1];
    const float* ew    = (const float*)d_in[2];
    const int*   ptei  = (const int*)  d_in[3];
    const float* pt    = (const float*)d_in[4];
    const float* alpha = (const float*)d_in[5];
    const float* gamma = (const float*)d_in[6];
    (void)in_sizes; (void)n_in; (void)out_size;

    float* out       = (float*)d_out;
    float* loss_slot = out + (size_t)NN * DD;
    float* w_out     = loss_slot + 1;

    k_init<<<(NN + 255) / 256, 256>>>(loss_slot);
    k_deg<<<(EE + 255) / 256, 256>>>(ei);
    k_dis<<<(NN + 255) / 256, 256>>>();
    k_scanA<<<SCAN_BLOCKS, 1024>>>();
    k_scanB<<<1, 32>>>();
    k_scanC<<<SCAN_BLOCKS, 1024>>>();
    k_scatter<<<(EE + 255) / 256, 256>>>(ei, ew);
    k_aggcsr<<<1184, 256>>>(x);
    k_pnorm<<<(PP * 32 + 255) / 256, 256>>>(pt);
    k_xstruct<<<(int)(((long long)NN * 32 + 255) / 256), 256>>>(x, gamma);
    k_kbuild<<<(NN + 63) / 64, 256>>>();
    for (int it = 1; it <= 19; it++) k_sink<<<592, 256>>>(it);
    k_epi<<<1184, 128>>>(x, pt, alpha, out, loss_slot);
    k_w<<<1184, 256>>>(ptei, w_out);
    k_wnorm<<<(EPTN + 255) / 256, 256>>>(w_out);
}

// round 4
// speedup vs baseline: 2.9927x; 2.1412x over previous
#include <cuda_runtime.h>
#include <cuda_fp16.h>

#define NN   100000
#define DD   128
#define PP   64
#define EE   3200000
#define EPTN 5000000
#define EPSI 0.1f
#define INVN (1.0f/100000.0f)
#define BV   (1.0f/64.0f)
#define SCAN_BLOCKS 98   // ceil(100000/1024)
#define SINK_BLOCKS 592  // one full wave: 148 SMs x 4 blocks

// -------- scratch (device globals; no dynamic allocation allowed) ----------
__device__ float g_deg[NN];
__device__ float g_dis[NN];
__device__ float g_xs[NN*DD];
__device__ float g_pn[PP*DD];
__device__ float g_K[(size_t)NN*PP];
__device__ float g_t[21*PP];
__device__ __half g_xfh[NN*DD];
__device__ unsigned int g_wmax;
// CSR scratch
__device__ int   g_rowcnt[NN];
__device__ int   g_rowstart[NN+1];
__device__ int   g_cursor[NN];
__device__ int2  g_csr[EE];
__device__ int   g_bsum[SCAN_BLOCKS];
__device__ unsigned int g_barcnt;

__device__ __forceinline__ float warp_sum(float v) {
    v += __shfl_xor_sync(0xffffffffu, v, 16);
    v += __shfl_xor_sync(0xffffffffu, v, 8);
    v += __shfl_xor_sync(0xffffffffu, v, 4);
    v += __shfl_xor_sync(0xffffffffu, v, 2);
    v += __shfl_xor_sync(0xffffffffu, v, 1);
    return v;
}

// ---------------------------------------------------------------------------
__global__ void k_init(float* loss_slot) {
    int idx = blockIdx.x * blockDim.x + threadIdx.x;
    if (idx < NN) { g_deg[idx] = 0.f; g_rowcnt[idx] = 0; }
    if (idx < 21*PP) g_t[idx] = 0.f;
    if (idx == 0) { g_wmax = 0u; g_barcnt = 0u; *loss_slot = 0.f; }
}

// degree of col (float) + count of row (int) in one pass
__global__ void k_deg(const int* __restrict__ ei) {
    int e = blockIdx.x * blockDim.x + threadIdx.x;
    if (e < EE) {
        atomicAdd(&g_deg[ei[EE + e]], 1.0f);
        atomicAdd(&g_rowcnt[ei[e]], 1);
    }
}

// ---- parallel scan (also computes deg^-1/2) -------------------------------
__global__ void k_scanA() {
    __shared__ int wsum[32];
    int tid = threadIdx.x, lane = tid & 31, w = tid >> 5;
    int i = blockIdx.x * 1024 + tid;
    if (i < NN) {
        float d = g_deg[i];
        g_dis[i] = (d > 0.f) ? rsqrtf(d) : 0.f;
    }
    int v = (i < NN) ? g_rowcnt[i] : 0;
    int s = v;
#pragma unroll
    for (int off = 1; off < 32; off <<= 1) {
        int n = __shfl_up_sync(0xffffffffu, s, off);
        if (lane >= off) s += n;
    }
    if (lane == 31) wsum[w] = s;
    __syncthreads();
    if (w == 0) {
        int t  = wsum[lane];
        int ts = t;
#pragma unroll
        for (int off = 1; off < 32; off <<= 1) {
            int n = __shfl_up_sync(0xffffffffu, ts, off);
            if (lane >= off) ts += n;
        }
        wsum[lane] = ts - t;
    }
    __syncthreads();
    int excl = wsum[w] + s - v;
    if (i < NN) g_rowstart[i] = excl;
    if (tid == 1023) g_bsum[blockIdx.x] = excl + v;
}

__global__ void k_scanB() {
    if (threadIdx.x == 0) {
        int acc = 0;
        for (int b = 0; b < SCAN_BLOCKS; b++) {
            int t = g_bsum[b];
            g_bsum[b] = acc;
            acc += t;
        }
    }
}

__global__ void k_scanC() {
    int i = blockIdx.x * 1024 + threadIdx.x;
    if (i < NN) {
        int v = g_rowstart[i] + g_bsum[blockIdx.x];
        g_rowstart[i] = v;
        g_cursor[i]   = v;
    }
    if (i == 0) g_rowstart[NN] = EE;
}

// scatter edges into CSR: one packed 8B store per edge
__global__ void k_scatter(const int* __restrict__ ei, const float* __restrict__ ew) {
    int e = blockIdx.x * blockDim.x + threadIdx.x;
    if (e >= EE) return;
    int r = ei[e];
    int c = ei[EE + e];
    float nw = g_dis[r] * ew[e] * g_dis[c];
    int pos = atomicAdd(&g_cursor[r], 1);
    g_csr[pos] = make_int2(c, __float_as_int(nw));
}

// warp per row: 4-edge-unrolled register accumulation; fused x_struct + l2norm
__global__ void k_aggcsr(const float* __restrict__ x, const float* __restrict__ gamma_p) {
    int tid = threadIdx.x;
    int lane = tid & 31;
    int warpId = (blockIdx.x * blockDim.x + tid) >> 5;
    int nW = (gridDim.x * blockDim.x) >> 5;
    float g = *gamma_p;
    for (int r = warpId; r < NN; r += nW) {
        int s = g_rowstart[r], e = g_rowstart[r + 1];
        float4 acc = make_float4(0.f, 0.f, 0.f, 0.f);
        int base = s;
        for (; base + 32 <= e; base += 32) {
            int2 cw = g_csr[base + lane];
            int cj = cw.x;
            float wj = __int_as_float(cw.y);
#pragma unroll
            for (int k = 0; k < 32; k += 4) {
                int   c0 = __shfl_sync(0xffffffffu, cj, k);
                int   c1 = __shfl_sync(0xffffffffu, cj, k + 1);
                int   c2 = __shfl_sync(0xffffffffu, cj, k + 2);
                int   c3 = __shfl_sync(0xffffffffu, cj, k + 3);
                float w0 = __shfl_sync(0xffffffffu, wj, k);
                float w1 = __shfl_sync(0xffffffffu, wj, k + 1);
                float w2 = __shfl_sync(0xffffffffu, wj, k + 2);
                float w3 = __shfl_sync(0xffffffffu, wj, k + 3);
                float4 v0 = *(const float4*)(x + (size_t)c0 * DD + lane * 4);
                float4 v1 = *(const float4*)(x + (size_t)c1 * DD + lane * 4);
                float4 v2 = *(const float4*)(x + (size_t)c2 * DD + lane * 4);
                float4 v3 = *(const float4*)(x + (size_t)c3 * DD + lane * 4);
                acc.x += w0 * v0.x; acc.y += w0 * v0.y; acc.z += w0 * v0.z; acc.w += w0 * v0.w;
                acc.x += w1 * v1.x; acc.y += w1 * v1.y; acc.z += w1 * v1.z; acc.w += w1 * v1.w;
                acc.x += w2 * v2.x; acc.y += w2 * v2.y; acc.z += w2 * v2.z; acc.w += w2 * v2.w;
                acc.x += w3 * v3.x; acc.y += w3 * v3.y; acc.z += w3 * v3.z; acc.w += w3 * v3.w;
            }
        }
        if (base < e) {
            int j = base + lane;
            int cj = 0; float wj = 0.f;
            if (j < e) { int2 cw = g_csr[j]; cj = cw.x; wj = __int_as_float(cw.y); }
            int cnt = e - base;
            for (int k = 0; k < cnt; k++) {
                int   ck = __shfl_sync(0xffffffffu, cj, k);
                float wk = __shfl_sync(0xffffffffu, wj, k);
                float4 v = *(const float4*)(x + (size_t)ck * DD + lane * 4);
                acc.x += wk * v.x; acc.y += wk * v.y; acc.z += wk * v.z; acc.w += wk * v.w;
            }
        }
        // fused x_struct + normalize
        float4 xv = *(const float4*)(x + (size_t)r * DD + lane * 4);
        float4 sv;
        sv.x = (1.f - g) * xv.x + g * acc.x;
        sv.y = (1.f - g) * xv.y + g * acc.y;
        sv.z = (1.f - g) * xv.z + g * acc.z;
        sv.w = (1.f - g) * xv.w + g * acc.w;
        float ss = warp_sum(sv.x*sv.x + sv.y*sv.y + sv.z*sv.z + sv.w*sv.w);
        float inv = 1.f / fmaxf(sqrtf(ss), 1e-12f);
        float4 o = make_float4(sv.x*inv, sv.y*inv, sv.z*inv, sv.w*inv);
        *(float4*)(g_xs + (size_t)r * DD + lane * 4) = o;
    }
}

// normalize prompt tokens (warp per prompt)
__global__ void k_pnorm(const float* __restrict__ pt) {
    int t = blockIdx.x * blockDim.x + threadIdx.x;
    int p = t >> 5, lane = t & 31;
    if (p >= PP) return;
    float4 v = *(const float4*)(pt + (size_t)p * DD + lane * 4);
    float ss = warp_sum(v.x*v.x + v.y*v.y + v.z*v.z + v.w*v.w);
    float inv = 1.f / fmaxf(sqrtf(ss), 1e-12f);
    float4 o = make_float4(v.x*inv, v.y*inv, v.z*inv, v.w*inv);
    *(float4*)(g_pn + (size_t)p * DD + lane * 4) = o;
}

// K[i][p] = exp(10*(cos-1)); also t0[p] = (1/N) * sum_i K[i][p]
__global__ void k_kbuild() {
    __shared__ float xs_sh[64][68];
    __shared__ float pn_sh[64][68];
    __shared__ float t_sh[PP];
    int tid = threadIdx.x;
    int tx = tid & 15;
    int ty = tid >> 4;
    int rowBase = blockIdx.x * 64;

    float acc[4][4];
#pragma unroll
    for (int i = 0; i < 4; i++)
#pragma unroll
        for (int j = 0; j < 4; j++) acc[i][j] = 0.f;

    for (int ch = 0; ch < 2; ch++) {
#pragma unroll
        for (int i = 0; i < 4; i++) {
            int rr = ty + i * 16;
            int c4 = tx * 4;
            int gr = rowBase + rr;
            float4 v = (gr < NN) ? *(const float4*)(g_xs + (size_t)gr * DD + ch * 64 + c4)
                                 : make_float4(0.f, 0.f, 0.f, 0.f);
            *(float4*)&xs_sh[rr][c4] = v;
            *(float4*)&pn_sh[rr][c4] = *(const float4*)(g_pn + (size_t)rr * DD + ch * 64 + c4);
        }
        __syncthreads();
#pragma unroll 8
        for (int d = 0; d < 64; d += 4) {
            float4 a[4], b[4];
#pragma unroll
            for (int i = 0; i < 4; i++) a[i] = *(float4*)&xs_sh[ty * 4 + i][d];
#pragma unroll
            for (int j = 0; j < 4; j++) b[j] = *(float4*)&pn_sh[tx * 4 + j][d];
#pragma unroll
            for (int i = 0; i < 4; i++)
#pragma unroll
                for (int j = 0; j < 4; j++) {
                    acc[i][j] += a[i].x * b[j].x;
                    acc[i][j] += a[i].y * b[j].y;
                    acc[i][j] += a[i].z * b[j].z;
                    acc[i][j] += a[i].w * b[j].w;
                }
        }
        __syncthreads();
    }

    if (tid < PP) t_sh[tid] = 0.f;
    __syncthreads();

    float colsum[4] = {0.f, 0.f, 0.f, 0.f};
#pragma unroll
    for (int i = 0; i < 4; i++) {
        int gr = rowBase + ty * 4 + i;
        if (gr < NN) {
            float4 kv;
            kv.x = __expf(10.f * (acc[i][0] - 1.f));
            kv.y = __expf(10.f * (acc[i][1] - 1.f));
            kv.z = __expf(10.f * (acc[i][2] - 1.f));
            kv.w = __expf(10.f * (acc[i][3] - 1.f));
            *(float4*)(g_K + (size_t)gr * PP + tx * 4) = kv;
            colsum[0] += kv.x; colsum[1] += kv.y; colsum[2] += kv.z; colsum[3] += kv.w;
        }
    }
#pragma unroll
    for (int j = 0; j < 4; j++) atomicAdd(&t_sh[tx * 4 + j], colsum[j]);
    __syncthreads();
    if (tid < PP) atomicAdd(&g_t[tid], t_sh[tid] * INVN);
}

// all 19 Sinkhorn iterations in ONE persistent kernel (1 wave, software barrier)
__global__ void __launch_bounds__(256) k_sinkall() {
    __shared__ float v_sh[PP];
    __shared__ float tacc[PP];
    int tid = threadIdx.x, lane = tid & 31;
    int warpId = (blockIdx.x * 256 + tid) >> 5;
    const int nW = (SINK_BLOCKS * 256) >> 5;   // 4736 warps

    for (int iter = 1; iter <= 19; iter++) {
        if (tid < PP) {
            v_sh[tid] = BV / (__ldcg(&g_t[(iter - 1) * PP + tid]) + 1e-30f);
            tacc[tid] = 0.f;
        }
        __syncthreads();
        float v0 = v_sh[2 * lane], v1 = v_sh[2 * lane + 1];
        float a0 = 0.f, a1 = 0.f;
        // NN % 4 == 0: all groups full
        for (int r0 = warpId * 4; r0 < NN; r0 += nW * 4) {
            float2 k2[4]; float s[4];
#pragma unroll
            for (int i = 0; i < 4; i++)
                k2[i] = *(const float2*)(g_K + (size_t)(r0 + i) * PP + 2 * lane);
#pragma unroll
            for (int i = 0; i < 4; i++) s[i] = k2[i].x * v0 + k2[i].y * v1;
#pragma unroll
            for (int i = 0; i < 4; i++) s[i] = warp_sum(s[i]);
#pragma unroll
            for (int i = 0; i < 4; i++) {
                float u = INVN / (s[i] + 1e-30f);
                a0 += k2[i].x * u;
                a1 += k2[i].y * u;
            }
        }
        // block-level smem reduction, then one global atomic per (block, p)
        atomicAdd(&tacc[2 * lane],     a0);
        atomicAdd(&tacc[2 * lane + 1], a1);
        __syncthreads();
        if (tid < PP) atomicAdd(&g_t[iter * PP + tid], tacc[tid]);
        __threadfence();
        __syncthreads();
        if (tid == 0) {
            atomicAdd(&g_barcnt, 1u);
            unsigned target = (unsigned)iter * gridDim.x;
            while (*(volatile unsigned*)&g_barcnt < target) { __nanosleep(64); }
        }
        __syncthreads();
    }
}

// epilogue: T*, ot_loss, prompt_message, x_adapted, xf (fp16)
__global__ void k_epi(const float* __restrict__ x, const float* __restrict__ pt,
                      const float* __restrict__ alpha_p,
                      float* __restrict__ out_x, float* __restrict__ loss_out) {
    __shared__ float pt_sh[PP][DD];
    __shared__ float T_sh[4][8][PP];
    __shared__ float v_sh[PP];
    int tid = threadIdx.x;
    for (int i = tid; i < PP * DD / 4; i += blockDim.x)
        ((float4*)&pt_sh[0][0])[i] = ((const float4*)pt)[i];
    if (tid < PP) v_sh[tid] = BV / (g_t[19 * PP + tid] + 1e-30f);
    __syncthreads();

    int lane = tid & 31, w = tid >> 5;
    int warpId = (blockIdx.x * blockDim.x + tid) >> 5;
    int nW = (gridDim.x * blockDim.x) >> 5;
    float v0 = v_sh[2 * lane], v1 = v_sh[2 * lane + 1];
    float scaleA = (*alpha_p) * (float)NN;
    float lossAcc = 0.f;

    for (int base = warpId * 8; base < NN; base += nW * 8) {
#pragma unroll
        for (int rr = 0; rr < 8; rr++) {
            int r = base + rr;
            float2 k2 = *(const float2*)(g_K + (size_t)r * PP + 2 * lane);
            float s = warp_sum(k2.x * v0 + k2.y * v1);
            float u = INVN / (s + 1e-30f);
            float T0 = u * k2.x * v0;
            float T1 = u * k2.y * v1;
            lossAcc += T0 * (-EPSI * __logf(k2.x)) + T1 * (-EPSI * __logf(k2.y));
            T_sh[w][rr][2 * lane]     = T0;
            T_sh[w][rr][2 * lane + 1] = T1;
        }
        __syncwarp();
        float4 pm[8];
#pragma unroll
        for (int rr = 0; rr < 8; rr++) pm[rr] = make_float4(0.f, 0.f, 0.f, 0.f);
#pragma unroll 4
        for (int p = 0; p < PP; p++) {
            float4 pv = *(const float4*)&pt_sh[p][lane * 4];
#pragma unroll
            for (int rr = 0; rr < 8; rr++) {
                float tp = T_sh[w][rr][p];
                pm[rr].x += tp * pv.x;
                pm[rr].y += tp * pv.y;
                pm[rr].z += tp * pv.z;
                pm[rr].w += tp * pv.w;
            }
        }
#pragma unroll
        for (int rr = 0; rr < 8; rr++) {
            int r = base + rr;
            float4 xv = *(const float4*)(x + (size_t)r * DD + lane * 4);
            float4 o;
            o.x = xv.x + scaleA * pm[rr].x;
            o.y = xv.y + scaleA * pm[rr].y;
            o.z = xv.z + scaleA * pm[rr].z;
            o.w = xv.w + scaleA * pm[rr].w;
            *(float4*)(out_x + (size_t)r * DD + lane * 4) = o;
            float ss = warp_sum(o.x*o.x + o.y*o.y + o.z*o.z + o.w*o.w);
            float inv = 1.f / fmaxf(sqrtf(ss), 1e-12f);
            __half2 h0 = __floats2half2_rn(o.x * inv, o.y * inv);
            __half2 h1 = __floats2half2_rn(o.z * inv, o.w * inv);
            uint2 packed;
            packed.x = *(unsigned int*)&h0;
            packed.y = *(unsigned int*)&h1;
            *(uint2*)(g_xfh + (size_t)r * DD + lane * 4) = packed;
        }
        __syncwarp();
    }
    lossAcc = warp_sum(lossAcc);
    if (lane == 0) atomicAdd(loss_out, lossAcc);
}

// w_e = relu(dot(xf[r], xf[c])); warp per edge, 4 edges in flight, fp16 gathers
__global__ void k_w(const int* __restrict__ ptei, float* __restrict__ w_out) {
    int tid = threadIdx.x;
    int lane = tid & 31;
    int warpId = (blockIdx.x * blockDim.x + tid) >> 5;
    int nW = (gridDim.x * blockDim.x) >> 5;
    float wmax = 0.f;
    for (int base = warpId * 4; base < EPTN; base += nW * 4) {
        int r[4], c[4];
#pragma unroll
        for (int q = 0; q < 4; q++) {
            r[q] = __ldg(&ptei[base + q]);
            c[q] = __ldg(&ptei[EPTN + base + q]);
        }
        float d[4];
#pragma unroll
        for (int q = 0; q < 4; q++) {
            uint2 ap = *(const uint2*)(g_xfh + (size_t)r[q] * DD + lane * 4);
            uint2 bp = *(const uint2*)(g_xfh + (size_t)c[q] * DD + lane * 4);
            float2 a0 = __half22float2(*(__half2*)&ap.x);
            float2 a1 = __half22float2(*(__half2*)&ap.y);
            float2 b0 = __half22float2(*(__half2*)&bp.x);
            float2 b1 = __half22float2(*(__half2*)&bp.y);
            d[q] = a0.x*b0.x + a0.y*b0.y + a1.x*b1.x + a1.y*b1.y;
        }
#pragma unroll
        for (int q = 0; q < 4; q++) {
            d[q] = warp_sum(d[q]);
            d[q] = fmaxf(d[q], 0.f);
            wmax = fmaxf(wmax, d[q]);
        }
        if (lane < 4) w_out[base + lane] = d[lane];
    }
    wmax = fmaxf(wmax, __shfl_xor_sync(0xffffffffu, wmax, 16));
    wmax = fmaxf(wmax, __shfl_xor_sync(0xffffffffu, wmax, 8));
    wmax = fmaxf(wmax, __shfl_xor_sync(0xffffffffu, wmax, 4));
    wmax = fmaxf(wmax, __shfl_xor_sync(0xffffffffu, wmax, 2));
    wmax = fmaxf(wmax, __shfl_xor_sync(0xffffffffu, wmax, 1));
    if (lane == 0) atomicMax(&g_wmax, __float_as_uint(wmax));
}

__global__ void k_wnorm(float* __restrict__ w_out) {
    int i = blockIdx.x * blockDim.x + threadIdx.x;
    if (i < EPTN) {
        float sc = 1.f / (__uint_as_float(g_wmax) + 1e-8f);
        w_out[i] *= sc;
    }
}

// ---------------------------------------------------------------------------
extern "C" void kernel_launch(void* const* d_in, const int* in_sizes, int n_in,
                              void* d_out, int out_size) {
    const float* x     = (const float*)d_in[0];
    const int*   ei    = (const int*)  d_in[1];
    const float* ew    = (const float*)d_in[2];
    const int*   ptei  = (const int*)  d_in[3];
    const float* pt    = (const float*)d_in[4];
    const float* alpha = (const float*)d_in[5];
    const float* gamma = (const float*)d_in[6];
    (void)in_sizes; (void)n_in; (void)out_size;

    float* out       = (float*)d_out;
    float* loss_slot = out + (size_t)NN * DD;
    float* w_out     = loss_slot + 1;

    k_init<<<(NN + 255) / 256, 256>>>(loss_slot);
    k_deg<<<(EE + 255) / 256, 256>>>(ei);
    k_scanA<<<SCAN_BLOCKS, 1024>>>();
    k_scanB<<<1, 32>>>();
    k_scanC<<<SCAN_BLOCKS, 1024>>>();
    k_scatter<<<(EE + 255) / 256, 256>>>(ei, ew);
    k_aggcsr<<<1184, 256>>>(x, gamma);
    k_pnorm<<<(PP * 32 + 255) / 256, 256>>>(pt);
    k_kbuild<<<(NN + 63) / 64, 256>>>();
    k_sinkall<<<SINK_BLOCKS, 256>>>();
    k_epi<<<1184, 128>>>(x, pt, alpha, out, loss_slot);
    k_w<<<1184, 256>>>(ptei, w_out);
    k_wnorm<<<(EPTN + 255) / 256, 256>>>(w_out);
}